// round 4
// baseline (speedup 1.0000x reference)
#include <cuda_runtime.h>

// ---------------- configuration ----------------
#define T        128
#define NTHREADS 256
#define MAXN     2097152

#define S1 136   // y1 row stride (134 real + pad)
#define S2 132   // y2/y3/y4/y5 row stride (130 real + pad)

// smem float offsets
#define OW1   0        // 100   w1T[t*20+co]
#define OB1   100      // 20
#define OW2   120      // 4000  w2T[(ci*5+t)*40+co]
#define OB2   4120     // 40
#define OW3   4160     // 3200  w3T[ci*80+co]
#define OB3   7360     // 80
#define OW4   7440     // 3200  w4T[ci*40+co]
#define OB4   10640    // 40
#define OW5   10680    // 2400  w5T[(ci*3+t)*20+co]
#define OB5   13080    // 20
#define OW6   13100    // 20
#define OB6   13120    // 1
#define ODIF  13124    // 140 (138 real + pad)
#define OY1   13264    // 20*136 = 2720 (reused for y5: 20*132)
#define OY2   15984    // 40*132 = 5280
#define OY3   21264    // 80*132 = 10560
#define OY4   31824    // 40*132 = 5280
#define SMEM_FLOATS 37104
#define SMEM_BYTES  (SMEM_FLOATS * 4)

__device__ float g_bm[MAXN];

__device__ __forceinline__ float elu1(float x) {
    float e = __expf(x) - 1.0f;
    return x > 0.0f ? x : e;
}

__global__ __launch_bounds__(NTHREADS)
void cnn_kernel(const float* __restrict__ uu,
                const float* __restrict__ w1, const float* __restrict__ b1,
                const float* __restrict__ w2, const float* __restrict__ b2,
                const float* __restrict__ w3, const float* __restrict__ b3,
                const float* __restrict__ w4, const float* __restrict__ b4,
                const float* __restrict__ w5, const float* __restrict__ b5,
                const float* __restrict__ w6, const float* __restrict__ b6,
                int N)
{
    extern __shared__ float s[];
    const int tid = threadIdx.x;
    const int g0  = blockIdx.x * T;

    // ---- load + transpose weights ----
    for (int i = tid; i < 100; i += NTHREADS) {           // w1 (20,1,5)
        int co = i / 5, t = i % 5;
        s[OW1 + t * 20 + co] = w1[i];
    }
    for (int i = tid; i < 20; i += NTHREADS)  s[OB1 + i] = b1[i];
    for (int i = tid; i < 4000; i += NTHREADS) {          // w2 (40,20,5)
        int co = i / 100, r = i % 100, ci = r / 5, t = r % 5;
        s[OW2 + (ci * 5 + t) * 40 + co] = w2[i];
    }
    for (int i = tid; i < 40; i += NTHREADS)  s[OB2 + i] = b2[i];
    for (int i = tid; i < 3200; i += NTHREADS) {          // w3 (80,40,1)
        int co = i / 40, ci = i % 40;
        s[OW3 + ci * 80 + co] = w3[i];
    }
    for (int i = tid; i < 80; i += NTHREADS)  s[OB3 + i] = b3[i];
    for (int i = tid; i < 3200; i += NTHREADS) {          // w4 (40,80,1)
        int co = i / 80, ci = i % 80;
        s[OW4 + ci * 40 + co] = w4[i];
    }
    for (int i = tid; i < 40; i += NTHREADS)  s[OB4 + i] = b4[i];
    for (int i = tid; i < 2400; i += NTHREADS) {          // w5 (20,40,3)
        int co = i / 120, r = i % 120, ci = r / 3, t = r % 3;
        s[OW5 + (ci * 3 + t) * 20 + co] = w5[i];
    }
    for (int i = tid; i < 20; i += NTHREADS)  s[OB5 + i] = b5[i];
    for (int i = tid; i < 20; i += NTHREADS)  s[OW6 + i] = w6[i];
    if (tid == 0) s[OB6] = b6[0];

    // ---- dif = avg_diff(uu), local window [g0-5, g0+133), padded to 140 ----
    for (int ld = tid; ld < 140; ld += NTHREADS) {
        int gd = g0 - 5 + ld;
        float v = 0.0f;
        if (ld < 138 && gd >= 0 && gd < N) {
            if (gd == 0)            v = __ldg(&uu[1]) - __ldg(&uu[0]);
            else if (gd == N - 1)   v = __ldg(&uu[N - 1]) - __ldg(&uu[N - 2]);
            else                    v = 0.5f * (__ldg(&uu[gd + 1]) - __ldg(&uu[gd - 1]));
        }
        s[ODIF + ld] = v;
    }
    __syncthreads();

    // ---- layer 1: 1 -> 20, k=5, pad 2. y1[lp] at gp = g0-3+lp, real lp<134 ----
    for (int item = tid; item < 20 * 136; item += NTHREADS) {
        int co = item / 136, lp = item % 136;
        float acc = s[OB1 + co];
        #pragma unroll
        for (int t = 0; t < 5; t++)
            acc += s[OW1 + t * 20 + co] * s[ODIF + lp + t];
        int gp = g0 - 3 + lp;
        float v = elu1(acc);
        if (lp >= 134 || gp < 0 || gp >= N) v = 0.0f;
        s[OY1 + co * S1 + lp] = v;
    }
    __syncthreads();

    // ---- layer 2: 20 -> 40, k=5, pad 2. y2[lp] at gp = g0-1+lp, real lp<130 ----
    // CO_T=5 (8 groups), P_T=4 (33 groups) -> 264 items
    for (int item = tid; item < 264; item += NTHREADS) {
        int cog = item & 7, posg = item >> 3;
        int co0 = cog * 5, lp0 = posg * 4;
        float acc[5][4];
        #pragma unroll
        for (int c = 0; c < 5; c++) {
            float b = s[OB2 + co0 + c];
            acc[c][0] = b; acc[c][1] = b; acc[c][2] = b; acc[c][3] = b;
        }
        for (int ci = 0; ci < 20; ci++) {
            const float* yr = &s[OY1 + ci * S1 + lp0];
            const float* wp = &s[OW2 + ci * 5 * 40 + co0];
            #pragma unroll
            for (int t = 0; t < 5; t++) {
                float a0 = yr[t], a1 = yr[t + 1], a2 = yr[t + 2], a3 = yr[t + 3];
                #pragma unroll
                for (int c = 0; c < 5; c++) {
                    float w = wp[t * 40 + c];
                    acc[c][0] += w * a0; acc[c][1] += w * a1;
                    acc[c][2] += w * a2; acc[c][3] += w * a3;
                }
            }
        }
        #pragma unroll
        for (int c = 0; c < 5; c++)
            #pragma unroll
            for (int p = 0; p < 4; p++) {
                int lp = lp0 + p, gp = g0 - 1 + lp;
                float v = elu1(acc[c][p]);
                if (lp >= 130 || gp < 0 || gp >= N) v = 0.0f;
                s[OY2 + (co0 + c) * S2 + lp] = v;
            }
    }
    __syncthreads();

    // ---- layer 3: 40 -> 80, k=1. CO_T=8 (10 groups), P_T=4 (33) -> 330 items ----
    for (int item = tid; item < 330; item += NTHREADS) {
        int cog = item % 10, posg = item / 10;
        int co0 = cog * 8, lp0 = posg * 4;
        float acc[8][4];
        #pragma unroll
        for (int c = 0; c < 8; c++) {
            float b = s[OB3 + co0 + c];
            acc[c][0] = b; acc[c][1] = b; acc[c][2] = b; acc[c][3] = b;
        }
        for (int ci = 0; ci < 40; ci++) {
            const float* yr = &s[OY2 + ci * S2 + lp0];
            float a0 = yr[0], a1 = yr[1], a2 = yr[2], a3 = yr[3];
            const float4* wp4 = reinterpret_cast<const float4*>(&s[OW3 + ci * 80 + co0]);
            float4 wa = wp4[0], wb = wp4[1];
            const float w8[8] = {wa.x, wa.y, wa.z, wa.w, wb.x, wb.y, wb.z, wb.w};
            #pragma unroll
            for (int c = 0; c < 8; c++) {
                acc[c][0] += w8[c] * a0; acc[c][1] += w8[c] * a1;
                acc[c][2] += w8[c] * a2; acc[c][3] += w8[c] * a3;
            }
        }
        #pragma unroll
        for (int c = 0; c < 8; c++)
            #pragma unroll
            for (int p = 0; p < 4; p++) {
                int lp = lp0 + p, gp = g0 - 1 + lp;
                float v = elu1(acc[c][p]);
                if (lp >= 130 || gp < 0 || gp >= N) v = 0.0f;
                s[OY3 + (co0 + c) * S2 + lp] = v;
            }
    }
    __syncthreads();

    // ---- layer 4: 80 -> 40, k=1. CO_T=5 (8 groups), P_T=4 (33) -> 264 items ----
    for (int item = tid; item < 264; item += NTHREADS) {
        int cog = item & 7, posg = item >> 3;
        int co0 = cog * 5, lp0 = posg * 4;
        float acc[5][4];
        #pragma unroll
        for (int c = 0; c < 5; c++) {
            float b = s[OB4 + co0 + c];
            acc[c][0] = b; acc[c][1] = b; acc[c][2] = b; acc[c][3] = b;
        }
        for (int ci = 0; ci < 80; ci++) {
            const float* yr = &s[OY3 + ci * S2 + lp0];
            float a0 = yr[0], a1 = yr[1], a2 = yr[2], a3 = yr[3];
            const float* wp = &s[OW4 + ci * 40 + co0];
            #pragma unroll
            for (int c = 0; c < 5; c++) {
                float w = wp[c];
                acc[c][0] += w * a0; acc[c][1] += w * a1;
                acc[c][2] += w * a2; acc[c][3] += w * a3;
            }
        }
        #pragma unroll
        for (int c = 0; c < 5; c++)
            #pragma unroll
            for (int p = 0; p < 4; p++) {
                int lp = lp0 + p, gp = g0 - 1 + lp;
                float v = elu1(acc[c][p]);
                if (lp >= 130 || gp < 0 || gp >= N) v = 0.0f;
                s[OY4 + (co0 + c) * S2 + lp] = v;
            }
    }
    __syncthreads();

    // ---- layer 5: 40 -> 20, k=3, pad 1. y5[lp] at gp = g0+lp, lp<128 ----
    // CO_T=5 (4 groups), P_T=2 (64 groups) -> 256 items. Writes into OY1.
    for (int item = tid; item < 256; item += NTHREADS) {
        int cog = item & 3, posg = item >> 2;
        int co0 = cog * 5, lp0 = posg * 2;
        float acc[5][2];
        #pragma unroll
        for (int c = 0; c < 5; c++) {
            float b = s[OB5 + co0 + c];
            acc[c][0] = b; acc[c][1] = b;
        }
        for (int ci = 0; ci < 40; ci++) {
            const float* yr = &s[OY4 + ci * S2 + lp0];
            const float* wp = &s[OW5 + ci * 3 * 20 + co0];
            #pragma unroll
            for (int t = 0; t < 3; t++) {
                float a0 = yr[t], a1 = yr[t + 1];
                #pragma unroll
                for (int c = 0; c < 5; c++) {
                    float w = wp[t * 20 + c];
                    acc[c][0] += w * a0; acc[c][1] += w * a1;
                }
            }
        }
        #pragma unroll
        for (int c = 0; c < 5; c++)
            #pragma unroll
            for (int p = 0; p < 2; p++) {
                int lp = lp0 + p, gp = g0 + lp;
                float v = elu1(acc[c][p]);
                if (gp >= N) v = 0.0f;
                s[OY1 + (co0 + c) * S2 + lp] = v;   // y5, stride S2
            }
    }
    __syncthreads();

    // ---- layer 6: 20 -> 1, k=1, sigmoid, + 0.1 ----
    for (int lp = tid; lp < T; lp += NTHREADS) {
        int gp = g0 + lp;
        if (gp < N) {
            float acc = s[OB6];
            #pragma unroll
            for (int c = 0; c < 20; c++)
                acc += s[OW6 + c] * s[OY1 + c * S2 + lp];
            float sg = 1.0f / (1.0f + __expf(-acc));
            g_bm[gp] = sg + 0.1f;
        }
    }
}

// ---------------- WENO reconstruction ----------------
__device__ __forceinline__ float weno_flux(float a, float b, float c, float d, float e,
                                           float bm_m1, float bm_0, float bm_p1)
{
    // stencil (umm, um, u, up, upp) = (a,b,c,d,e)
    const float C1312 = 13.0f / 12.0f;
    const float E = 1e-13f;
    float f0 = (11.0f * c - 7.0f * d + 2.0f * e) * (1.0f / 6.0f);
    float f1 = (2.0f * b + 5.0f * c - d) * (1.0f / 6.0f);
    float f2 = (-a + 5.0f * b + 2.0f * c) * (1.0f / 6.0f);

    float t0a = c - 2.0f * d + e, t0b = 3.0f * c - 4.0f * d + e;
    float t1a = b - 2.0f * c + d, t1b = b - d;
    float t2a = a - 2.0f * b + c, t2b = a - 4.0f * b + 3.0f * c;
    float b0 = C1312 * t0a * t0a + 0.25f * t0b * t0b;
    float b1 = C1312 * t1a * t1a + 0.25f * t1b * t1b;
    float b2 = C1312 * t2a * t2a + 0.25f * t2b * t2b;

    b0 *= bm_p1;  // roll(bm,-1)
    b1 *= bm_0;   // roll(bm, 0)
    b2 *= bm_m1;  // roll(bm, 1)

    float brs = (b2 - b0) * (b2 - b0);
    float e0 = (E + b0) * (E + b0);
    float e1 = (E + b1) * (E + b1);
    float e2 = (E + b2) * (E + b2);
    float om0 = 0.1f / e0 * (brs + e0);
    float om1 = 0.6f / e1 * (brs + e1);
    float om2 = 0.3f / e2 * (brs + e2);
    return (om0 * f0 + om1 * f1 + om2 * f2) / (om0 + om1 + om2);
}

__global__ void weno_kernel(const float* __restrict__ uu, float* __restrict__ out, int N)
{
    int i = blockIdx.x * blockDim.x + threadIdx.x;
    if (i >= N) return;
    int im2 = i - 2, im1 = i - 1, ip1 = i + 1, ip2 = i + 2, ip3 = i + 3;
    if (im2 < 0) im2 += N;
    if (im1 < 0) im1 += N;
    if (ip1 >= N) ip1 -= N;
    if (ip2 >= N) ip2 -= N;
    if (ip3 >= N) ip3 -= N;

    float umm = __ldg(&uu[im2]), um = __ldg(&uu[im1]), u0 = __ldg(&uu[i]);
    float up  = __ldg(&uu[ip1]), upp = __ldg(&uu[ip2]), uppp = __ldg(&uu[ip3]);
    float bm_m1 = g_bm[im1], bm_0 = g_bm[i], bm_p1 = g_bm[ip1];

    // positive flux: stencil shifted +1 (u_right = roll(uu,-1))
    float fluxp = weno_flux(um, u0, up, upp, uppp, bm_m1, bm_0, bm_p1);
    // negative flux
    float fluxn = weno_flux(umm, um, u0, up, upp, bm_m1, bm_0, bm_p1);

    out[i] = fluxp - fluxn;
}

extern "C" void kernel_launch(void* const* d_in, const int* in_sizes, int n_in,
                              void* d_out, int out_size)
{
    const float* uu = (const float*)d_in[0];
    const float* w1 = (const float*)d_in[1];
    const float* b1 = (const float*)d_in[2];
    const float* w2 = (const float*)d_in[3];
    const float* b2 = (const float*)d_in[4];
    const float* w3 = (const float*)d_in[5];
    const float* b3 = (const float*)d_in[6];
    const float* w4 = (const float*)d_in[7];
    const float* b4 = (const float*)d_in[8];
    const float* w5 = (const float*)d_in[9];
    const float* b5 = (const float*)d_in[10];
    const float* w6 = (const float*)d_in[11];
    const float* b6 = (const float*)d_in[12];
    float* out = (float*)d_out;
    int N = in_sizes[0];

    cudaFuncSetAttribute(cnn_kernel, cudaFuncAttributeMaxDynamicSharedMemorySize, SMEM_BYTES);

    int nb = (N + T - 1) / T;
    cnn_kernel<<<nb, NTHREADS, SMEM_BYTES>>>(uu, w1, b1, w2, b2, w3, b3, w4, b4,
                                             w5, b5, w6, b6, N);
    weno_kernel<<<(N + 255) / 256, 256>>>(uu, out, N);
}

// round 5
// speedup vs baseline: 1.3764x; 1.3764x over previous
#include <cuda_runtime.h>

// ---------------- configuration ----------------
#define T        128
#define NTHREADS 256
#define MAXN     2097152

#define S1 136   // y1 row stride (134 real + pad)
#define S2 132   // y2/y3/y4/y5 row stride (130 real + pad)

// smem float offsets
#define OW1   0        // 100   w1T[t*20+co]
#define OB1   100      // 20
#define OW2   120      // 4000  w2T[(ci*5+t)*40+co]
#define OB2   4120     // 40
#define OW3   4160     // 3200  w3T[ci*80+co]
#define OB3   7360     // 80
#define OW4   7440     // 3200  w4T[ci*40+co]
#define OB4   10640    // 40
#define OW5   10680    // 2400  w5T[(ci*3+t)*20+co]
#define OB5   13080    // 20
#define OW6   13100    // 20
#define OB6   13120    // 1
#define ODIF  13124    // 140 (138 real + pad)
#define OY1   13264    // 20*136 = 2720 (reused for y5: 20*132)
#define OY2   15984    // 40*132 = 5280
#define OY3   21264    // 80*132 = 10560
#define OY4   31824    // 40*132 = 5280
#define SMEM_FLOATS 37104
#define SMEM_BYTES  (SMEM_FLOATS * 4)

__device__ float g_bm[MAXN];

typedef unsigned long long u64;

// ---------------- f32x2 helpers (sm_100+ packed fp32) ----------------
__device__ __forceinline__ u64 splat2(float a) {
    u64 r; asm("mov.b64 %0, {%1, %1};" : "=l"(r) : "f"(a)); return r;
}
__device__ __forceinline__ u64 fma2(u64 a, u64 b, u64 c) {
    u64 d; asm("fma.rn.f32x2 %0, %1, %2, %3;" : "=l"(d) : "l"(a), "l"(b), "l"(c)); return d;
}
__device__ __forceinline__ void unpk(u64 v, float& x, float& y) {
    asm("mov.b64 {%0, %1}, %2;" : "=f"(x), "=f"(y) : "l"(v));
}

__device__ __forceinline__ float elu1(float x) {
    float e = __expf(x) - 1.0f;
    return x > 0.0f ? x : e;
}

__global__ __launch_bounds__(NTHREADS)
void cnn_kernel(const float* __restrict__ uu,
                const float* __restrict__ w1, const float* __restrict__ b1,
                const float* __restrict__ w2, const float* __restrict__ b2,
                const float* __restrict__ w3, const float* __restrict__ b3,
                const float* __restrict__ w4, const float* __restrict__ b4,
                const float* __restrict__ w5, const float* __restrict__ b5,
                const float* __restrict__ w6, const float* __restrict__ b6,
                int N)
{
    extern __shared__ float s[];
    const int tid = threadIdx.x;
    const int g0  = blockIdx.x * T;

    // ---- load + transpose weights ----
    for (int i = tid; i < 100; i += NTHREADS) {           // w1 (20,1,5)
        int co = i / 5, t = i % 5;
        s[OW1 + t * 20 + co] = w1[i];
    }
    for (int i = tid; i < 20; i += NTHREADS)  s[OB1 + i] = b1[i];
    for (int i = tid; i < 4000; i += NTHREADS) {          // w2 (40,20,5)
        int co = i / 100, r = i % 100, ci = r / 5, t = r % 5;
        s[OW2 + (ci * 5 + t) * 40 + co] = w2[i];
    }
    for (int i = tid; i < 40; i += NTHREADS)  s[OB2 + i] = b2[i];
    for (int i = tid; i < 3200; i += NTHREADS) {          // w3 (80,40,1)
        int co = i / 40, ci = i % 40;
        s[OW3 + ci * 80 + co] = w3[i];
    }
    for (int i = tid; i < 80; i += NTHREADS)  s[OB3 + i] = b3[i];
    for (int i = tid; i < 3200; i += NTHREADS) {          // w4 (40,80,1)
        int co = i / 80, ci = i % 80;
        s[OW4 + ci * 40 + co] = w4[i];
    }
    for (int i = tid; i < 40; i += NTHREADS)  s[OB4 + i] = b4[i];
    for (int i = tid; i < 2400; i += NTHREADS) {          // w5 (20,40,3)
        int co = i / 120, r = i % 120, ci = r / 3, t = r % 3;
        s[OW5 + (ci * 3 + t) * 20 + co] = w5[i];
    }
    for (int i = tid; i < 20; i += NTHREADS)  s[OB5 + i] = b5[i];
    for (int i = tid; i < 20; i += NTHREADS)  s[OW6 + i] = w6[i];
    if (tid == 0) s[OB6] = b6[0];

    // ---- dif = avg_diff(uu), local window [g0-5, g0+133), padded to 140 ----
    for (int ld = tid; ld < 140; ld += NTHREADS) {
        int gd = g0 - 5 + ld;
        float v = 0.0f;
        if (ld < 138 && gd >= 0 && gd < N) {
            if (gd == 0)            v = __ldg(&uu[1]) - __ldg(&uu[0]);
            else if (gd == N - 1)   v = __ldg(&uu[N - 1]) - __ldg(&uu[N - 2]);
            else                    v = 0.5f * (__ldg(&uu[gd + 1]) - __ldg(&uu[gd - 1]));
        }
        s[ODIF + ld] = v;
    }
    __syncthreads();

    // ---- layer 1: 1 -> 20, k=5, pad 2. y1[lp] at gp = g0-3+lp, real lp<134 ----
    for (int item = tid; item < 20 * 136; item += NTHREADS) {
        int co = item / 136, lp = item % 136;
        float acc = s[OB1 + co];
        #pragma unroll
        for (int t = 0; t < 5; t++)
            acc += s[OW1 + t * 20 + co] * s[ODIF + lp + t];
        int gp = g0 - 3 + lp;
        float v = elu1(acc);
        if (lp >= 134 || gp < 0 || gp >= N) v = 0.0f;
        s[OY1 + co * S1 + lp] = v;
    }
    __syncthreads();

    // ---- layer 2: 20 -> 40, k=5, pad 2. y2[lp] at gp = g0-1+lp, real lp<130 ----
    // 240 items: 20 cogroups (1 ch-pair) x 12 posgroups (P_T=11, covers 132)
    if (tid < 240) {
        const int cog = tid / 12, posg = tid % 12;
        const int co0 = cog * 2, lp0 = posg * 11;
        u64 acc[11];
        {
            u64 bp = *reinterpret_cast<const u64*>(&s[OB2 + co0]);
            #pragma unroll
            for (int p = 0; p < 11; p++) acc[p] = bp;
        }
        for (int ci = 0; ci < 20; ci++) {
            const float* yr = &s[OY1 + ci * S1 + lp0];
            const float* wp = &s[OW2 + ci * 5 * 40 + co0];
            u64 as[15];
            #pragma unroll
            for (int j = 0; j < 15; j++) as[j] = splat2(yr[j]);
            #pragma unroll
            for (int t = 0; t < 5; t++) {
                u64 w = *reinterpret_cast<const u64*>(&wp[t * 40]);
                #pragma unroll
                for (int p = 0; p < 11; p++)
                    acc[p] = fma2(w, as[t + p], acc[p]);
            }
        }
        #pragma unroll
        for (int p = 0; p < 11; p++) {
            int lp = lp0 + p, gp = g0 - 1 + lp;
            bool kill = (lp >= 130) | (gp < 0) | (gp >= N);
            float x, y; unpk(acc[p], x, y);
            float v0 = elu1(x), v1 = elu1(y);
            if (kill) { v0 = 0.0f; v1 = 0.0f; }
            s[OY2 + co0 * S2 + lp] = v0;
            s[OY2 + (co0 + 1) * S2 + lp] = v1;
        }
    }
    __syncthreads();

    // ---- layer 3: 40 -> 80, k=1. 220 items: 5 cog (8 ch-pairs) x 44 posg (P_T=3) ----
    if (tid < 220) {
        const int cog = tid / 44, posg = tid % 44;
        const int co0 = cog * 16, lp0 = posg * 3;
        u64 acc[8][3];
        #pragma unroll
        for (int c = 0; c < 8; c++) {
            u64 bp = *reinterpret_cast<const u64*>(&s[OB3 + co0 + 2 * c]);
            acc[c][0] = bp; acc[c][1] = bp; acc[c][2] = bp;
        }
        for (int ci = 0; ci < 40; ci++) {
            const float* yr = &s[OY2 + ci * S2 + lp0];
            u64 a0 = splat2(yr[0]), a1 = splat2(yr[1]), a2 = splat2(yr[2]);
            const u64* wp = reinterpret_cast<const u64*>(&s[OW3 + ci * 80 + co0]);
            #pragma unroll
            for (int c = 0; c < 8; c++) {
                u64 w = wp[c];
                acc[c][0] = fma2(w, a0, acc[c][0]);
                acc[c][1] = fma2(w, a1, acc[c][1]);
                acc[c][2] = fma2(w, a2, acc[c][2]);
            }
        }
        #pragma unroll
        for (int c = 0; c < 8; c++)
            #pragma unroll
            for (int p = 0; p < 3; p++) {
                int lp = lp0 + p, gp = g0 - 1 + lp;
                bool kill = (lp >= 130) | (gp < 0) | (gp >= N);
                float x, y; unpk(acc[c][p], x, y);
                float v0 = elu1(x), v1 = elu1(y);
                if (kill) { v0 = 0.0f; v1 = 0.0f; }
                s[OY3 + (co0 + 2 * c) * S2 + lp] = v0;
                s[OY3 + (co0 + 2 * c + 1) * S2 + lp] = v1;
            }
    }
    __syncthreads();

    // ---- layer 4: 80 -> 40, k=1. 220 items: 5 cog (4 ch-pairs) x 44 posg (P_T=3) ----
    if (tid < 220) {
        const int cog = tid / 44, posg = tid % 44;
        const int co0 = cog * 8, lp0 = posg * 3;
        u64 acc[4][3];
        #pragma unroll
        for (int c = 0; c < 4; c++) {
            u64 bp = *reinterpret_cast<const u64*>(&s[OB4 + co0 + 2 * c]);
            acc[c][0] = bp; acc[c][1] = bp; acc[c][2] = bp;
        }
        for (int ci = 0; ci < 80; ci++) {
            const float* yr = &s[OY3 + ci * S2 + lp0];
            u64 a0 = splat2(yr[0]), a1 = splat2(yr[1]), a2 = splat2(yr[2]);
            const u64* wp = reinterpret_cast<const u64*>(&s[OW4 + ci * 40 + co0]);
            #pragma unroll
            for (int c = 0; c < 4; c++) {
                u64 w = wp[c];
                acc[c][0] = fma2(w, a0, acc[c][0]);
                acc[c][1] = fma2(w, a1, acc[c][1]);
                acc[c][2] = fma2(w, a2, acc[c][2]);
            }
        }
        #pragma unroll
        for (int c = 0; c < 4; c++)
            #pragma unroll
            for (int p = 0; p < 3; p++) {
                int lp = lp0 + p, gp = g0 - 1 + lp;
                bool kill = (lp >= 130) | (gp < 0) | (gp >= N);
                float x, y; unpk(acc[c][p], x, y);
                float v0 = elu1(x), v1 = elu1(y);
                if (kill) { v0 = 0.0f; v1 = 0.0f; }
                s[OY4 + (co0 + 2 * c) * S2 + lp] = v0;
                s[OY4 + (co0 + 2 * c + 1) * S2 + lp] = v1;
            }
    }
    __syncthreads();

    // ---- layer 5: 40 -> 20, k=3, pad 1. y5[lp] at gp = g0+lp, real lp<128 ----
    // 215 items: 5 cog (2 ch-pairs) x 43 posg (P_T=3, covers 129). Writes into OY1.
    if (tid < 215) {
        const int cog = tid / 43, posg = tid % 43;
        const int co0 = cog * 4, lp0 = posg * 3;
        u64 acc[2][3];
        #pragma unroll
        for (int c = 0; c < 2; c++) {
            u64 bp = *reinterpret_cast<const u64*>(&s[OB5 + co0 + 2 * c]);
            acc[c][0] = bp; acc[c][1] = bp; acc[c][2] = bp;
        }
        for (int ci = 0; ci < 40; ci++) {
            const float* yr = &s[OY4 + ci * S2 + lp0];
            const float* wp = &s[OW5 + ci * 3 * 20 + co0];
            u64 as[5];
            #pragma unroll
            for (int j = 0; j < 5; j++) as[j] = splat2(yr[j]);
            #pragma unroll
            for (int t = 0; t < 3; t++) {
                u64 w0 = *reinterpret_cast<const u64*>(&wp[t * 20]);
                u64 w1 = *reinterpret_cast<const u64*>(&wp[t * 20 + 2]);
                #pragma unroll
                for (int p = 0; p < 3; p++) {
                    acc[0][p] = fma2(w0, as[t + p], acc[0][p]);
                    acc[1][p] = fma2(w1, as[t + p], acc[1][p]);
                }
            }
        }
        #pragma unroll
        for (int c = 0; c < 2; c++)
            #pragma unroll
            for (int p = 0; p < 3; p++) {
                int lp = lp0 + p, gp = g0 + lp;
                bool kill = (lp >= 128) | (gp >= N);
                float x, y; unpk(acc[c][p], x, y);
                float v0 = elu1(x), v1 = elu1(y);
                if (kill) { v0 = 0.0f; v1 = 0.0f; }
                s[OY1 + (co0 + 2 * c) * S2 + lp] = v0;
                s[OY1 + (co0 + 2 * c + 1) * S2 + lp] = v1;
            }
    }
    __syncthreads();

    // ---- layer 6: 20 -> 1, k=1, sigmoid, + 0.1 ----
    for (int lp = tid; lp < T; lp += NTHREADS) {
        int gp = g0 + lp;
        if (gp < N) {
            float acc = s[OB6];
            #pragma unroll
            for (int c = 0; c < 20; c++)
                acc += s[OW6 + c] * s[OY1 + c * S2 + lp];
            float sg = 1.0f / (1.0f + __expf(-acc));
            g_bm[gp] = sg + 0.1f;
        }
    }
}

// ---------------- WENO reconstruction ----------------
__device__ __forceinline__ float weno_flux(float a, float b, float c, float d, float e,
                                           float bm_m1, float bm_0, float bm_p1)
{
    const float C1312 = 13.0f / 12.0f;
    const float E = 1e-13f;
    float f0 = (11.0f * c - 7.0f * d + 2.0f * e) * (1.0f / 6.0f);
    float f1 = (2.0f * b + 5.0f * c - d) * (1.0f / 6.0f);
    float f2 = (-a + 5.0f * b + 2.0f * c) * (1.0f / 6.0f);

    float t0a = c - 2.0f * d + e, t0b = 3.0f * c - 4.0f * d + e;
    float t1a = b - 2.0f * c + d, t1b = b - d;
    float t2a = a - 2.0f * b + c, t2b = a - 4.0f * b + 3.0f * c;
    float b0 = C1312 * t0a * t0a + 0.25f * t0b * t0b;
    float b1 = C1312 * t1a * t1a + 0.25f * t1b * t1b;
    float b2 = C1312 * t2a * t2a + 0.25f * t2b * t2b;

    b0 *= bm_p1;
    b1 *= bm_0;
    b2 *= bm_m1;

    float brs = (b2 - b0) * (b2 - b0);
    float e0 = (E + b0) * (E + b0);
    float e1 = (E + b1) * (E + b1);
    float e2 = (E + b2) * (E + b2);
    float om0 = 0.1f / e0 * (brs + e0);
    float om1 = 0.6f / e1 * (brs + e1);
    float om2 = 0.3f / e2 * (brs + e2);
    return (om0 * f0 + om1 * f1 + om2 * f2) / (om0 + om1 + om2);
}

__global__ void weno_kernel(const float* __restrict__ uu, float* __restrict__ out, int N)
{
    int i = blockIdx.x * blockDim.x + threadIdx.x;
    if (i >= N) return;
    int im2 = i - 2, im1 = i - 1, ip1 = i + 1, ip2 = i + 2, ip3 = i + 3;
    if (im2 < 0) im2 += N;
    if (im1 < 0) im1 += N;
    if (ip1 >= N) ip1 -= N;
    if (ip2 >= N) ip2 -= N;
    if (ip3 >= N) ip3 -= N;

    float umm = __ldg(&uu[im2]), um = __ldg(&uu[im1]), u0 = __ldg(&uu[i]);
    float up  = __ldg(&uu[ip1]), upp = __ldg(&uu[ip2]), uppp = __ldg(&uu[ip3]);
    float bm_m1 = g_bm[im1], bm_0 = g_bm[i], bm_p1 = g_bm[ip1];

    float fluxp = weno_flux(um, u0, up, upp, uppp, bm_m1, bm_0, bm_p1);
    float fluxn = weno_flux(umm, um, u0, up, upp, bm_m1, bm_0, bm_p1);

    out[i] = fluxp - fluxn;
}

extern "C" void kernel_launch(void* const* d_in, const int* in_sizes, int n_in,
                              void* d_out, int out_size)
{
    const float* uu = (const float*)d_in[0];
    const float* w1 = (const float*)d_in[1];
    const float* b1 = (const float*)d_in[2];
    const float* w2 = (const float*)d_in[3];
    const float* b2 = (const float*)d_in[4];
    const float* w3 = (const float*)d_in[5];
    const float* b3 = (const float*)d_in[6];
    const float* w4 = (const float*)d_in[7];
    const float* b4 = (const float*)d_in[8];
    const float* w5 = (const float*)d_in[9];
    const float* b5 = (const float*)d_in[10];
    const float* w6 = (const float*)d_in[11];
    const float* b6 = (const float*)d_in[12];
    float* out = (float*)d_out;
    int N = in_sizes[0];

    cudaFuncSetAttribute(cnn_kernel, cudaFuncAttributeMaxDynamicSharedMemorySize, SMEM_BYTES);

    int nb = (N + T - 1) / T;
    cnn_kernel<<<nb, NTHREADS, SMEM_BYTES>>>(uu, w1, b1, w2, b2, w3, b3, w4, b4,
                                             w5, b5, w6, b6, N);
    weno_kernel<<<(N + 255) / 256, 256>>>(uu, out, N);
}